// round 11
// baseline (speedup 1.0000x reference)
#include <cuda_runtime.h>
#include <cuda_bf16.h>
#include <cstdint>
#include <math.h>

// Problem constants
#define E_DIM 1024
#define H_NUM 16
#define HD 64
#define R_RANK 16
#define T_LEN 2048
#define B_SZ 2
#define S_LEN 2048
#define M_ROWS (T_LEN * B_SZ)   // 4096
#define BH (B_SZ * H_NUM)       // 32

// ---------------------------------------------------------------------------
// Persistent scratch — GEMM operands pre-split hi/lo bf16
// ---------------------------------------------------------------------------
__device__ __align__(16) __nv_bfloat16 g_whi[4][E_DIM * E_DIM];
__device__ __align__(16) __nv_bfloat16 g_wlo[4][E_DIM * E_DIM];
__device__ __align__(16) __nv_bfloat16 g_ihi[3][M_ROWS * E_DIM];
__device__ __align__(16) __nv_bfloat16 g_ilo[3][M_ROWS * E_DIM];
__device__ __align__(16) __nv_bfloat16 g_qhi[M_ROWS * E_DIM];
__device__ __align__(16) __nv_bfloat16 g_qlo[M_ROWS * E_DIM];
__device__ __align__(16) __nv_bfloat16 g_khi[M_ROWS * E_DIM];
__device__ __align__(16) __nv_bfloat16 g_klo[M_ROWS * E_DIM];
__device__ float g_v[M_ROWS * E_DIM];
__device__ __align__(16) __nv_bfloat16 g_vthi[(size_t)BH * HD * S_LEN];
__device__ __align__(16) __nv_bfloat16 g_vtlo[(size_t)BH * HD * S_LEN];
__device__ __align__(16) __nv_bfloat16 g_aohi[M_ROWS * E_DIM];
__device__ __align__(16) __nv_bfloat16 g_aolo[M_ROWS * E_DIM];
__device__ __align__(16) __nv_bfloat16 g_phi[(size_t)BH * T_LEN * S_LEN];  // E hi (for mean)
__device__ float g_invsum[(size_t)BH * T_LEN];      // 1 / sum_s E

// ===========================================================================
// Helpers
// ===========================================================================
__device__ __forceinline__ uint32_t smem_u32(const void* p) {
    uint32_t a;
    asm("{ .reg .u64 t; cvta.to.shared.u64 t, %1; cvt.u32.u64 %0, t; }" : "=r"(a) : "l"(p));
    return a;
}
__device__ __forceinline__ void ldm_x4(uint32_t* r, uint32_t addr) {
    asm volatile("ldmatrix.sync.aligned.m8n8.x4.shared.b16 {%0,%1,%2,%3}, [%4];"
                 : "=r"(r[0]), "=r"(r[1]), "=r"(r[2]), "=r"(r[3]) : "r"(addr));
}
__device__ __forceinline__ void mma16816(float* c, const uint32_t* a, const uint32_t* b) {
    asm volatile(
        "mma.sync.aligned.m16n8k16.row.col.f32.bf16.bf16.f32 "
        "{%0,%1,%2,%3}, {%4,%5,%6,%7}, {%8,%9}, {%0,%1,%2,%3};"
        : "+f"(c[0]), "+f"(c[1]), "+f"(c[2]), "+f"(c[3])
        : "r"(a[0]), "r"(a[1]), "r"(a[2]), "r"(a[3]), "r"(b[0]), "r"(b[1]));
}
__device__ __forceinline__ void cp16(uint32_t s, const __nv_bfloat16* g) {
    asm volatile("cp.async.cg.shared.global [%0], [%1], 16;"
                 :: "r"(s), "l"(__cvta_generic_to_global(g)));
}
#define CP_COMMIT() asm volatile("cp.async.commit_group;" ::: "memory")
#define CP_WAIT0()  asm volatile("cp.async.wait_group 0;" ::: "memory")
#define CP_WAIT1()  asm volatile("cp.async.wait_group 1;" ::: "memory")

__device__ __forceinline__ void split1(float y, __nv_bfloat16& h, __nv_bfloat16& l) {
    h = __float2bfloat16(y);
    l = __float2bfloat16(y - __bfloat162float(h));
}
__device__ __forceinline__ unsigned pack2(__nv_bfloat16 a, __nv_bfloat16 b) {
    __nv_bfloat162 t(a, b);
    return reinterpret_cast<unsigned&>(t);
}
__device__ __forceinline__ float2 unp2(unsigned u) {
    __nv_bfloat162 t = reinterpret_cast<__nv_bfloat162&>(u);
    return __bfloat1622float2(t);
}

// ===========================================================================
// Generic GEMM core: C = scale*(A@B^T) + bias
// MODE 0: fp32 out. MODE 1: hi/lo pair out. BM=128, BK=32, BN=128.
// 3-stage cp.async pipeline, depth-2 prefetch, ONE __syncthreads per iter.
// ===========================================================================
template <int BN, int MODE>
__device__ __forceinline__ void gemm_core(
    const __nv_bfloat16* __restrict__ Ahi, const __nv_bfloat16* __restrict__ Alo, int lda,
    const __nv_bfloat16* __restrict__ Bhi, const __nv_bfloat16* __restrict__ Blo, int ldb,
    float* __restrict__ Cf,
    __nv_bfloat16* __restrict__ Chi, __nv_bfloat16* __restrict__ Clo, int ldc,
    const float* __restrict__ bias, float scale, int K)
{
    constexpr int BM = 128;
    constexpr int SK = 40;
    constexpr int WN = BN / 2;
    constexpr int NP = WN / 16;
    constexpr int ATILE = BM * SK;
    constexpr int BTILE = BN * SK;
    constexpr int STAGE = 2 * ATILE + 2 * BTILE;

    extern __shared__ __nv_bfloat16 sm[];

    const int tid = threadIdx.x;
    const int wid = tid >> 5;
    const int lane = tid & 31;
    const int wm0 = (wid >> 1) * 32;
    const int wn0 = (wid & 1) * WN;

    Ahi += (size_t)(blockIdx.y * BM) * lda;
    Alo += (size_t)(blockIdx.y * BM) * lda;
    Bhi += (size_t)(blockIdx.x * BN) * ldb;
    Blo += (size_t)(blockIdx.x * BN) * ldb;
    const size_t cOff = (size_t)(blockIdx.y * BM) * ldc + blockIdx.x * BN;
    if (bias) bias += blockIdx.x * BN;

    const uint32_t sb = smem_u32(sm);

    float acc[2][2 * NP][4];
#pragma unroll
    for (int i = 0; i < 2; i++)
#pragma unroll
        for (int j = 0; j < 2 * NP; j++)
#pragma unroll
            for (int q = 0; q < 4; q++) acc[i][j][q] = 0.0f;

    const int a_row = lane & 15;
    const int a_col = (lane >> 4) << 3;
    const int b_row = (lane & 7) + ((lane >> 4) << 3);
    const int b_col = ((lane >> 3) & 1) << 3;

    const int nch = K >> 5;

    auto load_stage = [&](int it, int st) {
        const uint32_t s0 = sb + st * (STAGE * 2);
        const int k0 = it * 32;
#pragma unroll
        for (int l = 0; l < 2; l++) {
            int idx = tid + l * 256;
            int r = idx >> 2, c = idx & 3;
            size_t g = (size_t)r * lda + k0 + c * 8;
            uint32_t so = (uint32_t)(r * SK + c * 8) * 2;
            cp16(s0 + so, Ahi + g);
            cp16(s0 + ATILE * 2 + so, Alo + g);
        }
#pragma unroll
        for (int l = 0; l < BN / 64; l++) {
            int idx = tid + l * 256;
            int r = idx >> 2, c = idx & 3;
            size_t g = (size_t)r * ldb + k0 + c * 8;
            uint32_t so = (uint32_t)(r * SK + c * 8) * 2;
            cp16(s0 + 2 * ATILE * 2 + so, Bhi + g);
            cp16(s0 + (2 * ATILE + BTILE) * 2 + so, Blo + g);
        }
    };

    load_stage(0, 0);
    CP_COMMIT();
    load_stage(1, 1);
    CP_COMMIT();

    for (int it = 0; it < nch; ++it) {
        const int st = it % 3;
        if (it < nch - 1) CP_WAIT1(); else CP_WAIT0();
        __syncthreads();
        if (it + 2 < nch) { load_stage(it + 2, (it + 2) % 3); CP_COMMIT(); }

        const uint32_t offAh = sb + st * (STAGE * 2);
        const uint32_t offAl = offAh + ATILE * 2;
        const uint32_t offBh = offAl + ATILE * 2;
        const uint32_t offBl = offBh + BTILE * 2;

#pragma unroll
        for (int kk = 0; kk < 2; kk++) {
            uint32_t ah[2][4], al[2][4];
#pragma unroll
            for (int mi = 0; mi < 2; mi++) {
                uint32_t ea = ((wm0 + mi * 16 + a_row) * SK + kk * 16 + a_col) * 2;
                ldm_x4(ah[mi], offAh + ea);
                ldm_x4(al[mi], offAl + ea);
            }
#pragma unroll
            for (int pi = 0; pi < NP; pi++) {
                uint32_t bh4[4], bl4[4];
                uint32_t eb = ((wn0 + pi * 16 + b_row) * SK + kk * 16 + b_col) * 2;
                ldm_x4(bh4, offBh + eb);
                ldm_x4(bl4, offBl + eb);
                uint32_t bh0[2] = {bh4[0], bh4[1]}, bh1[2] = {bh4[2], bh4[3]};
                uint32_t bl0[2] = {bl4[0], bl4[1]}, bl1[2] = {bl4[2], bl4[3]};
#pragma unroll
                for (int mi = 0; mi < 2; mi++) {
                    mma16816(acc[mi][2 * pi + 0], ah[mi], bh0);
                    mma16816(acc[mi][2 * pi + 1], ah[mi], bh1);
                    mma16816(acc[mi][2 * pi + 0], ah[mi], bl0);
                    mma16816(acc[mi][2 * pi + 1], ah[mi], bl1);
                    mma16816(acc[mi][2 * pi + 0], al[mi], bh0);
                    mma16816(acc[mi][2 * pi + 1], al[mi], bh1);
                }
            }
        }
    }

    const int er = lane >> 2;
    const int ec = (lane & 3) * 2;
#pragma unroll
    for (int mi = 0; mi < 2; mi++) {
#pragma unroll
        for (int fi = 0; fi < 2 * NP; fi++) {
            int row = wm0 + mi * 16 + er;
            int col = wn0 + fi * 8 + ec;
            float bx = 0.f, by = 0.f;
            if (bias) { bx = bias[col]; by = bias[col + 1]; }
            float y0 = acc[mi][fi][0] * scale + bx;
            float y1 = acc[mi][fi][1] * scale + by;
            float y2 = acc[mi][fi][2] * scale + bx;
            float y3 = acc[mi][fi][3] * scale + by;
            size_t o0 = cOff + (size_t)row * ldc + col;
            size_t o1 = cOff + (size_t)(row + 8) * ldc + col;
            if (MODE == 0) {
                *(float2*)(Cf + o0) = make_float2(y0, y1);
                *(float2*)(Cf + o1) = make_float2(y2, y3);
            } else {
                __nv_bfloat16 h0, l0, h1, l1, h2, l2, h3, l3;
                split1(y0, h0, l0); split1(y1, h1, l1);
                split1(y2, h2, l2); split1(y3, h3, l3);
                *(unsigned*)(Chi + o0) = pack2(h0, h1);
                *(unsigned*)(Clo + o0) = pack2(l0, l1);
                *(unsigned*)(Chi + o1) = pack2(h2, h3);
                *(unsigned*)(Clo + o1) = pack2(l2, l3);
            }
        }
    }
}

template <int BN, int MODE>
__global__ __launch_bounds__(256) void gemm_pair(
    const __nv_bfloat16* __restrict__ Ahi, const __nv_bfloat16* __restrict__ Alo, int lda,
    const __nv_bfloat16* __restrict__ Bhi, const __nv_bfloat16* __restrict__ Blo, int ldb,
    float* __restrict__ Cf,
    __nv_bfloat16* __restrict__ Chi, __nv_bfloat16* __restrict__ Clo, int ldc,
    const float* __restrict__ bias, float scale, int K)
{
    gemm_core<BN, MODE>(Ahi, Alo, lda, Bhi, Blo, ldb, Cf, Chi, Clo, ldc, bias, scale, K);
}

// Merged Q/K/V projection
struct ProjPtrs {
    const __nv_bfloat16* ahi[3]; const __nv_bfloat16* alo[3];
    const __nv_bfloat16* bhi[3]; const __nv_bfloat16* blo[3];
    const float* bias[3];
    float* cf[3];
    __nv_bfloat16* chi[3]; __nv_bfloat16* clo[3];
    int outmode[3];
};
__global__ __launch_bounds__(256) void proj_gemm(ProjPtrs p) {
    const int z = blockIdx.z;
    if (p.outmode[z] == 0)
        gemm_core<128, 0>(p.ahi[z], p.alo[z], E_DIM, p.bhi[z], p.blo[z], E_DIM,
                          p.cf[z], nullptr, nullptr, E_DIM, p.bias[z], 1.0f, E_DIM);
    else
        gemm_core<128, 1>(p.ahi[z], p.alo[z], E_DIM, p.bhi[z], p.blo[z], E_DIM,
                          nullptr, p.chi[z], p.clo[z], E_DIM, p.bias[z], 1.0f, E_DIM);
}

// ===========================================================================
// FUSED ATTENTION: per CTA = (bh, 128 t-rows). s-loop in 64-chunks,
// 3-stage K/V pipeline with depth-2 prefetch.
// QK 3-term MMA -> exp -> E-hi staged+coalesced out -> P frags -> PV 3-term MMA.
// End: cross-warp O reduce, rowsum->invsum, normalize, write ao pair.
// ===========================================================================
__global__ __launch_bounds__(256, 1) void fused_attn() {
    constexpr int SKQ = 72, SKC = 72, SEW = 72;
    constexpr int QHI = 0;
    constexpr int QLO = 128 * SKQ;                 // 9216
    constexpr int STG = 2 * 128 * SKQ;             // 18432
    constexpr int SSZ = 4 * 64 * SKC;              // 18432 per stage
    constexpr int KHI = 0, KLO = 64 * SKC, VHI = 2 * 64 * SKC, VLO = 3 * 64 * SKC;
    constexpr int SE  = STG + 3 * SSZ;             // 73728
    // total = SE + 128*SEW = 82944 elems = 165888 B

    extern __shared__ __nv_bfloat16 sm[];
    const uint32_t sb = smem_u32(sm);

    const int tid = threadIdx.x;
    const int wid = tid >> 5;
    const int lane = tid & 31;
    const int wm0 = (wid >> 1) * 32;
    const int wn0 = (wid & 1) * 32;
    const int z = blockIdx.z;                  // bh
    const int b = z >> 4, h = z & 15;
    const int t0 = blockIdx.x * 128;

    const __nv_bfloat16* Qh = g_qhi + (size_t)b * 1024 + h * 64 + (size_t)t0 * 2048;
    const __nv_bfloat16* Ql = g_qlo + (size_t)b * 1024 + h * 64 + (size_t)t0 * 2048;
    const __nv_bfloat16* Kh = g_khi + (size_t)b * 1024 + h * 64;
    const __nv_bfloat16* Kl = g_klo + (size_t)b * 1024 + h * 64;
    const __nv_bfloat16* Vh = g_vthi + (size_t)z * HD * S_LEN;
    const __nv_bfloat16* Vl = g_vtlo + (size_t)z * HD * S_LEN;
    __nv_bfloat16* Eh = g_phi + (size_t)z * T_LEN * S_LEN + (size_t)t0 * 2048;

    // Q tile load (128 x 64 hi/lo)
#pragma unroll
    for (int l = 0; l < 4; l++) {
        int idx = tid + l * 256;
        int r = idx >> 3, c = idx & 7;
        cp16(sb + (uint32_t)(QHI + r * SKQ + c * 8) * 2, Qh + (size_t)r * 2048 + c * 8);
        cp16(sb + (uint32_t)(QLO + r * SKQ + c * 8) * 2, Ql + (size_t)r * 2048 + c * 8);
    }

    auto load_stage = [&](int sc, int st) {
        const uint32_t s0 = sb + (uint32_t)(STG + st * SSZ) * 2;
        const size_t srow = (size_t)sc * 64 * 2048;
#pragma unroll
        for (int l = 0; l < 2; l++) {
            int idx = tid + l * 256;
            int r = idx >> 3, c = idx & 7;
            size_t gk = srow + (size_t)r * 2048 + c * 8;
            size_t gv = (size_t)r * 2048 + sc * 64 + c * 8;
            uint32_t so = (uint32_t)(r * SKC + c * 8) * 2;
            cp16(s0 + (uint32_t)KHI * 2 + so, Kh + gk);
            cp16(s0 + (uint32_t)KLO * 2 + so, Kl + gk);
            cp16(s0 + (uint32_t)VHI * 2 + so, Vh + gv);
            cp16(s0 + (uint32_t)VLO * 2 + so, Vl + gv);
        }
    };

    load_stage(0, 0);
    CP_COMMIT();
    load_stage(1, 1);
    CP_COMMIT();

    float acc_o[2][8][4];
#pragma unroll
    for (int i = 0; i < 2; i++)
#pragma unroll
        for (int j = 0; j < 8; j++)
#pragma unroll
            for (int q = 0; q < 4; q++) acc_o[i][j][q] = 0.0f;
    float rowpart[2][2] = {{0.f, 0.f}, {0.f, 0.f}};

    const int a_row = lane & 15;
    const int a_col = (lane >> 4) << 3;
    const int b_row = (lane & 7) + ((lane >> 4) << 3);
    const int b_col = ((lane >> 3) & 1) << 3;
    const int er = lane >> 2;
    const int ec = (lane & 3) * 2;

    for (int sc = 0; sc < 32; ++sc) {
        const int st = sc % 3;
        if (sc < 31) CP_WAIT1(); else CP_WAIT0();
        __syncthreads();
        if (sc + 2 < 32) { load_stage(sc + 2, (sc + 2) % 3); CP_COMMIT(); }

        const uint32_t sK = sb + (uint32_t)(STG + st * SSZ) * 2;

        // --- QK: 128x64 scores chunk, 3-term, k over d=64 ---
        float acc_s[2][4][4];
#pragma unroll
        for (int i = 0; i < 2; i++)
#pragma unroll
            for (int j = 0; j < 4; j++)
#pragma unroll
                for (int q = 0; q < 4; q++) acc_s[i][j][q] = 0.0f;

#pragma unroll
        for (int kk = 0; kk < 4; kk++) {
            uint32_t ah[2][4], al[2][4];
#pragma unroll
            for (int mi = 0; mi < 2; mi++) {
                uint32_t ea = (uint32_t)((wm0 + mi * 16 + a_row) * SKQ + kk * 16 + a_col) * 2;
                ldm_x4(ah[mi], sb + (uint32_t)QHI * 2 + ea);
                ldm_x4(al[mi], sb + (uint32_t)QLO * 2 + ea);
            }
#pragma unroll
            for (int pi = 0; pi < 2; pi++) {
                uint32_t bh4[4], bl4[4];
                uint32_t eb = (uint32_t)((wn0 + pi * 16 + b_row) * SKC + kk * 16 + b_col) * 2;
                ldm_x4(bh4, sK + (uint32_t)KHI * 2 + eb);
                ldm_x4(bl4, sK + (uint32_t)KLO * 2 + eb);
                uint32_t bh0[2] = {bh4[0], bh4[1]}, bh1[2] = {bh4[2], bh4[3]};
                uint32_t bl0[2] = {bl4[0], bl4[1]}, bl1[2] = {bl4[2], bl4[3]};
#pragma unroll
                for (int mi = 0; mi < 2; mi++) {
                    mma16816(acc_s[mi][2 * pi + 0], ah[mi], bh0);
                    mma16816(acc_s[mi][2 * pi + 1], ah[mi], bh1);
                    mma16816(acc_s[mi][2 * pi + 0], ah[mi], bl0);
                    mma16816(acc_s[mi][2 * pi + 1], ah[mi], bl1);
                    mma16816(acc_s[mi][2 * pi + 0], al[mi], bh0);
                    mma16816(acc_s[mi][2 * pi + 1], al[mi], bh1);
                }
            }
        }

        // --- exp, rowsum partials, stage E-hi ---
#pragma unroll
        for (int mi = 0; mi < 2; mi++) {
#pragma unroll
            for (int fi = 0; fi < 4; fi++) {
                float e0 = __expf(acc_s[mi][fi][0] * 0.125f);
                float e1 = __expf(acc_s[mi][fi][1] * 0.125f);
                float e2 = __expf(acc_s[mi][fi][2] * 0.125f);
                float e3 = __expf(acc_s[mi][fi][3] * 0.125f);
                acc_s[mi][fi][0] = e0; acc_s[mi][fi][1] = e1;
                acc_s[mi][fi][2] = e2; acc_s[mi][fi][3] = e3;
                rowpart[mi][0] += e0 + e1;
                rowpart[mi][1] += e2 + e3;
                int row = wm0 + mi * 16 + er;
                int col = wn0 + fi * 8 + ec;
                *(unsigned*)&sm[SE + row * SEW + col] =
                    pack2(__float2bfloat16(e0), __float2bfloat16(e1));
                *(unsigned*)&sm[SE + (row + 8) * SEW + col] =
                    pack2(__float2bfloat16(e2), __float2bfloat16(e3));
            }
        }

        // --- PV: P(128 x 64chunk) @ V(64chunk x 64d) ---
#pragma unroll
        for (int kp = 0; kp < 2; kp++) {
            uint32_t ph[2][4], pl[2][4];
#pragma unroll
            for (int mi = 0; mi < 2; mi++) {
                const float* c0 = acc_s[mi][2 * kp];
                const float* c1 = acc_s[mi][2 * kp + 1];
                __nv_bfloat16 ha, la, hb, lb2;
                split1(c0[0], ha, la); split1(c0[1], hb, lb2);
                ph[mi][0] = pack2(ha, hb); pl[mi][0] = pack2(la, lb2);
                split1(c0[2], ha, la); split1(c0[3], hb, lb2);
                ph[mi][1] = pack2(ha, hb); pl[mi][1] = pack2(la, lb2);
                split1(c1[0], ha, la); split1(c1[1], hb, lb2);
                ph[mi][2] = pack2(ha, hb); pl[mi][2] = pack2(la, lb2);
                split1(c1[2], ha, la); split1(c1[3], hb, lb2);
                ph[mi][3] = pack2(ha, hb); pl[mi][3] = pack2(la, lb2);
            }
#pragma unroll
            for (int nt = 0; nt < 4; nt++) {
                uint32_t vh4[4], vl4[4];
                uint32_t eb = (uint32_t)((nt * 16 + b_row) * SKC + wn0 + kp * 16 + b_col) * 2;
                ldm_x4(vh4, sK + (uint32_t)VHI * 2 + eb);
                ldm_x4(vl4, sK + (uint32_t)VLO * 2 + eb);
                uint32_t vh0[2] = {vh4[0], vh4[1]}, vh1[2] = {vh4[2], vh4[3]};
                uint32_t vl0[2] = {vl4[0], vl4[1]}, vl1[2] = {vl4[2], vl4[3]};
#pragma unroll
                for (int mi = 0; mi < 2; mi++) {
                    mma16816(acc_o[mi][2 * nt + 0], ph[mi], vh0);
                    mma16816(acc_o[mi][2 * nt + 1], ph[mi], vh1);
                    mma16816(acc_o[mi][2 * nt + 0], ph[mi], vl0);
                    mma16816(acc_o[mi][2 * nt + 1], ph[mi], vl1);
                    mma16816(acc_o[mi][2 * nt + 0], pl[mi], vh0);
                    mma16816(acc_o[mi][2 * nt + 1], pl[mi], vh1);
                }
            }
        }

        __syncthreads();
        // --- coalesced E-hi copy-out ---
#pragma unroll
        for (int l = 0; l < 4; l++) {
            int idx = tid + l * 256;
            int r = idx >> 3, c8 = idx & 7;
            uint4 v = *(uint4*)&sm[SE + r * SEW + c8 * 8];
            *(uint4*)(Eh + (size_t)r * 2048 + sc * 64 + c8 * 8) = v;
        }
    }

    // --- row sums -> invsum ---
    __shared__ float psmem[128][2];
    __shared__ float sinv[128];
#pragma unroll
    for (int mi = 0; mi < 2; mi++)
#pragma unroll
        for (int rh = 0; rh < 2; rh++) {
            float v = rowpart[mi][rh];
            v += __shfl_xor_sync(0xffffffffu, v, 1);
            v += __shfl_xor_sync(0xffffffffu, v, 2);
            if ((lane & 3) == 0)
                psmem[wm0 + mi * 16 + rh * 8 + er][wid & 1] = v;
        }
    __syncthreads();
    if (tid < 128) {
        float s = psmem[tid][0] + psmem[tid][1];
        float inv = 1.0f / s;
        sinv[tid] = inv;
        g_invsum[(size_t)z * T_LEN + t0 + tid] = inv;
    }

    // --- O reduce across the two n-half warps ---
    float* sO = (float*)(sm + STG);        // 128 x 68 fp32 (aliases dead stages)
    if ((wid & 1) == 0) {
#pragma unroll
        for (int mi = 0; mi < 2; mi++)
#pragma unroll
            for (int nt8 = 0; nt8 < 8; nt8++) {
                int row = wm0 + mi * 16 + er;
                int col = nt8 * 8 + ec;
                *(float2*)&sO[row * 68 + col] =
                    make_float2(acc_o[mi][nt8][0], acc_o[mi][nt8][1]);
                *(float2*)&sO[(row + 8) * 68 + col] =
                    make_float2(acc_o[mi][nt8][2], acc_o[mi][nt8][3]);
            }
    }
    __syncthreads();
    if ((wid & 1) == 1) {
#pragma unroll
        for (int mi = 0; mi < 2; mi++)
#pragma unroll
            for (int nt8 = 0; nt8 < 8; nt8++) {
                int row = wm0 + mi * 16 + er;
                int col = nt8 * 8 + ec;
                float2 p0 = *(float2*)&sO[row * 68 + col];
                float2 p1 = *(float2*)&sO[(row + 8) * 68 + col];
                float i0 = sinv[row], i1 = sinv[row + 8];
                float y0 = (p0.x + acc_o[mi][nt8][0]) * i0;
                float y1 = (p0.y + acc_o[mi][nt8][1]) * i0;
                float y2 = (p1.x + acc_o[mi][nt8][2]) * i1;
                float y3 = (p1.y + acc_o[mi][nt8][3]) * i1;
                __nv_bfloat16 h0, l0, h1, l1, h2, l2, h3, l3;
                split1(y0, h0, l0); split1(y1, h1, l1);
                split1(y2, h2, l2); split1(y3, h3, l3);
                size_t o0 = (size_t)(t0 + row) * 2048 + (size_t)z * 64 + col;
                size_t o1 = (size_t)(t0 + row + 8) * 2048 + (size_t)z * 64 + col;
                *(unsigned*)(g_aohi + o0) = pack2(h0, h1);
                *(unsigned*)(g_aolo + o0) = pack2(l0, l1);
                *(unsigned*)(g_aohi + o1) = pack2(h2, h3);
                *(unsigned*)(g_aolo + o1) = pack2(l2, l3);
            }
    }
}

// ---------------------------------------------------------------------------
// Merged weff: Weff = w + lb@la -> hi/lo pair
// ---------------------------------------------------------------------------
struct WeffPtrs { const float* w[4]; const float* la[4]; const float* lb[4]; };
__global__ __launch_bounds__(256) void weff_all(WeffPtrs p) {
    const int widx = blockIdx.y;
    int idx = blockIdx.x * 256 + threadIdx.x;
    int j = idx & (E_DIM - 1);
    int i = idx >> 10;
    float acc = p.w[widx][idx];
#pragma unroll
    for (int r = 0; r < R_RANK; r++)
        acc += p.lb[widx][i * R_RANK + r] * p.la[widx][r * E_DIM + j];
    __nv_bfloat16 h, l;
    split1(acc, h, l);
    g_whi[widx][idx] = h;
    g_wlo[widx][idx] = l;
}

// ---------------------------------------------------------------------------
// Merged input fp32 -> hi/lo pair
// ---------------------------------------------------------------------------
struct InPtrs { const float* in[3]; };
__global__ __launch_bounds__(256) void cvt_all(InPtrs p) {
    const int which = blockIdx.y;
    int i = blockIdx.x * 256 + threadIdx.x;
    float4 v = ((const float4*)p.in[which])[i];
    __nv_bfloat16 hx, lx, hy, ly, hz, lz, hw, lw;
    split1(v.x, hx, lx); split1(v.y, hy, ly);
    split1(v.z, hz, lz); split1(v.w, hw, lw);
    ((uint2*)g_ihi[which])[i] = make_uint2(pack2(hx, hy), pack2(hz, hw));
    ((uint2*)g_ilo[which])[i] = make_uint2(pack2(lx, ly), pack2(lz, lw));
}

// ---------------------------------------------------------------------------
// Transpose V -> per-head V^T hi/lo
// ---------------------------------------------------------------------------
__global__ void vt_kernel() {
    __shared__ float t[32][33];
    const int z = blockIdx.z;
    const int b = z >> 4, h = z & 15;
    const int s0 = blockIdx.x * 32;
    const int d0 = blockIdx.y * 32;
    const int tx = threadIdx.x, ty = threadIdx.y;
#pragma unroll
    for (int i = 0; i < 4; i++) {
        int s = s0 + ty + i * 8;
        t[ty + i * 8][tx] = g_v[((size_t)s * B_SZ + b) * E_DIM + h * HD + d0 + tx];
    }
    __syncthreads();
#pragma unroll
    for (int i = 0; i < 4; i++) {
        int d = d0 + ty + i * 8;
        float x = t[tx][ty + i * 8];
        __nv_bfloat16 hh, ll;
        split1(x, hh, ll);
        size_t o = ((size_t)z * HD + d) * S_LEN + s0 + tx;
        g_vthi[o] = hh;
        g_vtlo[o] = ll;
    }
}

// ---------------------------------------------------------------------------
// attn_w mean (E-hi, invsum): one block per (b,t)
// ---------------------------------------------------------------------------
__global__ __launch_bounds__(256) void mean_kernel(float* __restrict__ outMean) {
    const int bt = blockIdx.x;
    const int b = bt >> 11, t = bt & 2047;
    const int tid = threadIdx.x;

    __shared__ float wsc[16];
    if (tid < 16)
        wsc[tid] = g_invsum[(size_t)(b * 16 + tid) * T_LEN + t] * (1.0f / 16.0f);
    __syncthreads();

    float a0[4] = {0.f, 0.f, 0.f, 0.f};
    float a1[4] = {0.f, 0.f, 0.f, 0.f};
#pragma unroll 4
    for (int h = 0; h < 16; h++) {
        const size_t base = ((size_t)(b * 16 + h) * T_LEN + t) * S_LEN;
        const float wh = wsc[h];
        uint2 hi0 = ((const uint2*)(g_phi + base))[tid];
        uint2 hi1 = ((const uint2*)(g_phi + base))[tid + 256];
        float2 hA = unp2(hi0.x), hB = unp2(hi0.y);
        a0[0] += hA.x * wh; a0[1] += hA.y * wh;
        a0[2] += hB.x * wh; a0[3] += hB.y * wh;
        hA = unp2(hi1.x); hB = unp2(hi1.y);
        a1[0] += hA.x * wh; a1[1] += hA.y * wh;
        a1[2] += hB.x * wh; a1[3] += hB.y * wh;
    }

    float4* mrow = (float4*)(outMean + (size_t)bt * S_LEN);
    mrow[tid] = make_float4(a0[0], a0[1], a0[2], a0[3]);
    mrow[tid + 256] = make_float4(a1[0], a1[1], a1[2], a1[3]);
}

// ---------------------------------------------------------------------------
extern "C" void kernel_launch(void* const* d_in, const int* in_sizes, int n_in,
                              void* d_out, int out_size) {
    const float* query = (const float*)d_in[0];
    const float* key   = (const float*)d_in[1];
    const float* value = (const float*)d_in[2];
    const float* w[4]    = {(const float*)d_in[3],  (const float*)d_in[7],
                            (const float*)d_in[11], (const float*)d_in[15]};
    const float* bias[4] = {(const float*)d_in[4],  (const float*)d_in[8],
                            (const float*)d_in[12], (const float*)d_in[16]};
    const float* la[4]   = {(const float*)d_in[5],  (const float*)d_in[9],
                            (const float*)d_in[13], (const float*)d_in[17]};
    const float* lb[4]   = {(const float*)d_in[6],  (const float*)d_in[10],
                            (const float*)d_in[14], (const float*)d_in[18]};
    float* out = (float*)d_out;

    __nv_bfloat16 *p_whi, *p_wlo, *p_ihi, *p_ilo, *p_qhi, *p_qlo, *p_khi, *p_klo;
    __nv_bfloat16 *p_aohi, *p_aolo;
    float *p_v;
    cudaGetSymbolAddress((void**)&p_whi, g_whi);
    cudaGetSymbolAddress((void**)&p_wlo, g_wlo);
    cudaGetSymbolAddress((void**)&p_ihi, g_ihi);
    cudaGetSymbolAddress((void**)&p_ilo, g_ilo);
    cudaGetSymbolAddress((void**)&p_qhi, g_qhi);
    cudaGetSymbolAddress((void**)&p_qlo, g_qlo);
    cudaGetSymbolAddress((void**)&p_khi, g_khi);
    cudaGetSymbolAddress((void**)&p_klo, g_klo);
    cudaGetSymbolAddress((void**)&p_aohi, g_aohi);
    cudaGetSymbolAddress((void**)&p_aolo, g_aolo);
    cudaGetSymbolAddress((void**)&p_v, g_v);

    const size_t WSZ = (size_t)E_DIM * E_DIM;
    const size_t ISZ = (size_t)M_ROWS * E_DIM;

    const int SMEM128 = 3 * (2 * 128 * 40 + 2 * 128 * 40) * 2;  // 122880
    const int SMEM_F  = 165888;
    cudaFuncSetAttribute(gemm_pair<128, 0>, cudaFuncAttributeMaxDynamicSharedMemorySize, SMEM128);
    cudaFuncSetAttribute(proj_gemm, cudaFuncAttributeMaxDynamicSharedMemorySize, SMEM128);
    cudaFuncSetAttribute(fused_attn, cudaFuncAttributeMaxDynamicSharedMemorySize, SMEM_F);

    // Fold LoRA
    WeffPtrs wp;
    for (int i = 0; i < 4; i++) { wp.w[i] = w[i]; wp.la[i] = la[i]; wp.lb[i] = lb[i]; }
    weff_all<<<dim3(E_DIM * E_DIM / 256, 4), 256>>>(wp);

    // Inputs -> pair
    InPtrs ip = {{query, key, value}};
    cvt_all<<<dim3(ISZ / 4 / 256, 3), 256>>>(ip);

    // Q/K/V projections
    ProjPtrs pp;
    for (int zi = 0; zi < 3; zi++) {
        pp.ahi[zi] = p_ihi + zi * ISZ;
        pp.alo[zi] = p_ilo + zi * ISZ;
        pp.bhi[zi] = p_whi + zi * WSZ;
        pp.blo[zi] = p_wlo + zi * WSZ;
        pp.bias[zi] = bias[zi];
    }
    pp.cf[0] = nullptr; pp.chi[0] = p_qhi; pp.clo[0] = p_qlo; pp.outmode[0] = 1;
    pp.cf[1] = nullptr; pp.chi[1] = p_khi; pp.clo[1] = p_klo; pp.outmode[1] = 1;
    pp.cf[2] = p_v;     pp.chi[2] = nullptr; pp.clo[2] = nullptr; pp.outmode[2] = 0;
    proj_gemm<<<dim3(8, 32, 3), 256, SMEM128>>>(pp);

    // V^T pair
    vt_kernel<<<dim3(S_LEN / 32, HD / 32, BH), dim3(32, 8)>>>();

    // Fused attention: E-hi + invsum + ao pair
    fused_attn<<<dim3(16, 1, 32), 256, SMEM_F>>>();

    // attn_w mean -> out tail
    mean_kernel<<<B_SZ * T_LEN, 256>>>(out + (size_t)T_LEN * B_SZ * E_DIM);

    // Output projection -> d_out
    gemm_pair<128, 0><<<dim3(8, 32, 1), 256, SMEM128>>>(
        p_aohi, p_aolo, E_DIM,
        p_whi + 3 * WSZ, p_wlo + 3 * WSZ, E_DIM,
        out, nullptr, nullptr, E_DIM, bias[3], 1.0f, E_DIM);
}

// round 12
// speedup vs baseline: 1.1333x; 1.1333x over previous
#include <cuda_runtime.h>
#include <cuda_bf16.h>
#include <cstdint>
#include <math.h>

// Problem constants
#define E_DIM 1024
#define H_NUM 16
#define HD 64
#define R_RANK 16
#define T_LEN 2048
#define B_SZ 2
#define S_LEN 2048
#define M_ROWS (T_LEN * B_SZ)   // 4096
#define BH (B_SZ * H_NUM)       // 32

// ---------------------------------------------------------------------------
// Persistent scratch — GEMM operands pre-split hi/lo bf16
// ---------------------------------------------------------------------------
__device__ __align__(16) __nv_bfloat16 g_whi[4][E_DIM * E_DIM];
__device__ __align__(16) __nv_bfloat16 g_wlo[4][E_DIM * E_DIM];
__device__ __align__(16) __nv_bfloat16 g_ihi[3][M_ROWS * E_DIM];
__device__ __align__(16) __nv_bfloat16 g_ilo[3][M_ROWS * E_DIM];
__device__ __align__(16) __nv_bfloat16 g_qhi[M_ROWS * E_DIM];
__device__ __align__(16) __nv_bfloat16 g_qlo[M_ROWS * E_DIM];
__device__ __align__(16) __nv_bfloat16 g_khi[M_ROWS * E_DIM];
__device__ __align__(16) __nv_bfloat16 g_klo[M_ROWS * E_DIM];
__device__ float g_v[M_ROWS * E_DIM];
__device__ __align__(16) __nv_bfloat16 g_vthi[(size_t)BH * HD * S_LEN];
__device__ __align__(16) __nv_bfloat16 g_vtlo[(size_t)BH * HD * S_LEN];
__device__ __align__(16) __nv_bfloat16 g_aohi[M_ROWS * E_DIM];
__device__ __align__(16) __nv_bfloat16 g_aolo[M_ROWS * E_DIM];
__device__ __align__(16) __nv_bfloat16 g_phi[(size_t)BH * T_LEN * S_LEN];  // E hi (for mean)
__device__ float g_invsum[(size_t)BH * T_LEN];      // 1 / sum_s E

// ===========================================================================
// Helpers
// ===========================================================================
__device__ __forceinline__ uint32_t smem_u32(const void* p) {
    uint32_t a;
    asm("{ .reg .u64 t; cvta.to.shared.u64 t, %1; cvt.u32.u64 %0, t; }" : "=r"(a) : "l"(p));
    return a;
}
__device__ __forceinline__ void ldm_x4(uint32_t* r, uint32_t addr) {
    asm volatile("ldmatrix.sync.aligned.m8n8.x4.shared.b16 {%0,%1,%2,%3}, [%4];"
                 : "=r"(r[0]), "=r"(r[1]), "=r"(r[2]), "=r"(r[3]) : "r"(addr));
}
__device__ __forceinline__ void mma16816(float* c, const uint32_t* a, const uint32_t* b) {
    asm volatile(
        "mma.sync.aligned.m16n8k16.row.col.f32.bf16.bf16.f32 "
        "{%0,%1,%2,%3}, {%4,%5,%6,%7}, {%8,%9}, {%0,%1,%2,%3};"
        : "+f"(c[0]), "+f"(c[1]), "+f"(c[2]), "+f"(c[3])
        : "r"(a[0]), "r"(a[1]), "r"(a[2]), "r"(a[3]), "r"(b[0]), "r"(b[1]));
}
__device__ __forceinline__ void cp16(uint32_t s, const __nv_bfloat16* g) {
    asm volatile("cp.async.cg.shared.global [%0], [%1], 16;"
                 :: "r"(s), "l"(__cvta_generic_to_global(g)));
}
#define CP_COMMIT() asm volatile("cp.async.commit_group;" ::: "memory")
#define CP_WAIT0()  asm volatile("cp.async.wait_group 0;" ::: "memory")
#define CP_WAIT1()  asm volatile("cp.async.wait_group 1;" ::: "memory")

__device__ __forceinline__ void split1(float y, __nv_bfloat16& h, __nv_bfloat16& l) {
    h = __float2bfloat16(y);
    l = __float2bfloat16(y - __bfloat162float(h));
}
__device__ __forceinline__ unsigned pack2(__nv_bfloat16 a, __nv_bfloat16 b) {
    __nv_bfloat162 t(a, b);
    return reinterpret_cast<unsigned&>(t);
}
__device__ __forceinline__ float2 unp2(unsigned u) {
    __nv_bfloat162 t = reinterpret_cast<__nv_bfloat162&>(u);
    return __bfloat1622float2(t);
}

// ===========================================================================
// Generic GEMM core (round-10 proven): C = scale*(A@B^T) + bias
// MODE 0: fp32 out. MODE 1: hi/lo pair out. BM=128, BK=32, BN=128.
// 2-stage cp.async double buffer.
// ===========================================================================
template <int BN, int MODE>
__device__ __forceinline__ void gemm_core(
    const __nv_bfloat16* __restrict__ Ahi, const __nv_bfloat16* __restrict__ Alo, int lda,
    const __nv_bfloat16* __restrict__ Bhi, const __nv_bfloat16* __restrict__ Blo, int ldb,
    float* __restrict__ Cf,
    __nv_bfloat16* __restrict__ Chi, __nv_bfloat16* __restrict__ Clo, int ldc,
    const float* __restrict__ bias, float scale, int K)
{
    constexpr int BM = 128;
    constexpr int SK = 40;
    constexpr int WN = BN / 2;
    constexpr int NP = WN / 16;
    constexpr int ATILE = BM * SK;
    constexpr int BTILE = BN * SK;
    constexpr int STAGE = 2 * ATILE + 2 * BTILE;

    extern __shared__ __nv_bfloat16 sm[];

    const int tid = threadIdx.x;
    const int wid = tid >> 5;
    const int lane = tid & 31;
    const int wm0 = (wid >> 1) * 32;
    const int wn0 = (wid & 1) * WN;

    Ahi += (size_t)(blockIdx.y * BM) * lda;
    Alo += (size_t)(blockIdx.y * BM) * lda;
    Bhi += (size_t)(blockIdx.x * BN) * ldb;
    Blo += (size_t)(blockIdx.x * BN) * ldb;
    const size_t cOff = (size_t)(blockIdx.y * BM) * ldc + blockIdx.x * BN;
    if (bias) bias += blockIdx.x * BN;

    const uint32_t sb = smem_u32(sm);

    float acc[2][2 * NP][4];
#pragma unroll
    for (int i = 0; i < 2; i++)
#pragma unroll
        for (int j = 0; j < 2 * NP; j++)
#pragma unroll
            for (int q = 0; q < 4; q++) acc[i][j][q] = 0.0f;

    const int a_row = lane & 15;
    const int a_col = (lane >> 4) << 3;
    const int b_row = (lane & 7) + ((lane >> 4) << 3);
    const int b_col = ((lane >> 3) & 1) << 3;

    const int nch = K >> 5;

    auto load_stage = [&](int it, int st) {
        const uint32_t s0 = sb + st * (STAGE * 2);
        const int k0 = it * 32;
#pragma unroll
        for (int l = 0; l < 2; l++) {
            int idx = tid + l * 256;
            int r = idx >> 2, c = idx & 3;
            size_t g = (size_t)r * lda + k0 + c * 8;
            uint32_t so = (uint32_t)(r * SK + c * 8) * 2;
            cp16(s0 + so, Ahi + g);
            cp16(s0 + ATILE * 2 + so, Alo + g);
        }
#pragma unroll
        for (int l = 0; l < BN / 64; l++) {
            int idx = tid + l * 256;
            int r = idx >> 2, c = idx & 3;
            size_t g = (size_t)r * ldb + k0 + c * 8;
            uint32_t so = (uint32_t)(r * SK + c * 8) * 2;
            cp16(s0 + 2 * ATILE * 2 + so, Bhi + g);
            cp16(s0 + (2 * ATILE + BTILE) * 2 + so, Blo + g);
        }
    };

    load_stage(0, 0);
    CP_COMMIT();

    for (int it = 0; it < nch; ++it) {
        const int st = it & 1;
        if (it + 1 < nch) { load_stage(it + 1, st ^ 1); CP_COMMIT(); CP_WAIT1(); }
        else              { CP_WAIT0(); }
        __syncthreads();

        const uint32_t offAh = sb + st * (STAGE * 2);
        const uint32_t offAl = offAh + ATILE * 2;
        const uint32_t offBh = offAl + ATILE * 2;
        const uint32_t offBl = offBh + BTILE * 2;

#pragma unroll
        for (int kk = 0; kk < 2; kk++) {
            uint32_t ah[2][4], al[2][4];
#pragma unroll
            for (int mi = 0; mi < 2; mi++) {
                uint32_t ea = ((wm0 + mi * 16 + a_row) * SK + kk * 16 + a_col) * 2;
                ldm_x4(ah[mi], offAh + ea);
                ldm_x4(al[mi], offAl + ea);
            }
#pragma unroll
            for (int pi = 0; pi < NP; pi++) {
                uint32_t bh4[4], bl4[4];
                uint32_t eb = ((wn0 + pi * 16 + b_row) * SK + kk * 16 + b_col) * 2;
                ldm_x4(bh4, offBh + eb);
                ldm_x4(bl4, offBl + eb);
                uint32_t bh0[2] = {bh4[0], bh4[1]}, bh1[2] = {bh4[2], bh4[3]};
                uint32_t bl0[2] = {bl4[0], bl4[1]}, bl1[2] = {bl4[2], bl4[3]};
#pragma unroll
                for (int mi = 0; mi < 2; mi++) {
                    mma16816(acc[mi][2 * pi + 0], ah[mi], bh0);
                    mma16816(acc[mi][2 * pi + 1], ah[mi], bh1);
                    mma16816(acc[mi][2 * pi + 0], ah[mi], bl0);
                    mma16816(acc[mi][2 * pi + 1], ah[mi], bl1);
                    mma16816(acc[mi][2 * pi + 0], al[mi], bh0);
                    mma16816(acc[mi][2 * pi + 1], al[mi], bh1);
                }
            }
        }
        __syncthreads();
    }

    const int er = lane >> 2;
    const int ec = (lane & 3) * 2;
#pragma unroll
    for (int mi = 0; mi < 2; mi++) {
#pragma unroll
        for (int fi = 0; fi < 2 * NP; fi++) {
            int row = wm0 + mi * 16 + er;
            int col = wn0 + fi * 8 + ec;
            float bx = 0.f, by = 0.f;
            if (bias) { bx = bias[col]; by = bias[col + 1]; }
            float y0 = acc[mi][fi][0] * scale + bx;
            float y1 = acc[mi][fi][1] * scale + by;
            float y2 = acc[mi][fi][2] * scale + bx;
            float y3 = acc[mi][fi][3] * scale + by;
            size_t o0 = cOff + (size_t)row * ldc + col;
            size_t o1 = cOff + (size_t)(row + 8) * ldc + col;
            if (MODE == 0) {
                *(float2*)(Cf + o0) = make_float2(y0, y1);
                *(float2*)(Cf + o1) = make_float2(y2, y3);
            } else {
                __nv_bfloat16 h0, l0, h1, l1, h2, l2, h3, l3;
                split1(y0, h0, l0); split1(y1, h1, l1);
                split1(y2, h2, l2); split1(y3, h3, l3);
                *(unsigned*)(Chi + o0) = pack2(h0, h1);
                *(unsigned*)(Clo + o0) = pack2(l0, l1);
                *(unsigned*)(Chi + o1) = pack2(h2, h3);
                *(unsigned*)(Clo + o1) = pack2(l2, l3);
            }
        }
    }
}

template <int BN, int MODE>
__global__ __launch_bounds__(256) void gemm_pair(
    const __nv_bfloat16* __restrict__ Ahi, const __nv_bfloat16* __restrict__ Alo, int lda,
    const __nv_bfloat16* __restrict__ Bhi, const __nv_bfloat16* __restrict__ Blo, int ldb,
    float* __restrict__ Cf,
    __nv_bfloat16* __restrict__ Chi, __nv_bfloat16* __restrict__ Clo, int ldc,
    const float* __restrict__ bias, float scale, int K)
{
    gemm_core<BN, MODE>(Ahi, Alo, lda, Bhi, Blo, ldb, Cf, Chi, Clo, ldc, bias, scale, K);
}

// Merged Q/K/V projection
struct ProjPtrs {
    const __nv_bfloat16* ahi[3]; const __nv_bfloat16* alo[3];
    const __nv_bfloat16* bhi[3]; const __nv_bfloat16* blo[3];
    const float* bias[3];
    float* cf[3];
    __nv_bfloat16* chi[3]; __nv_bfloat16* clo[3];
    int outmode[3];
};
__global__ __launch_bounds__(256) void proj_gemm(ProjPtrs p) {
    const int z = blockIdx.z;
    if (p.outmode[z] == 0)
        gemm_core<128, 0>(p.ahi[z], p.alo[z], E_DIM, p.bhi[z], p.blo[z], E_DIM,
                          p.cf[z], nullptr, nullptr, E_DIM, p.bias[z], 1.0f, E_DIM);
    else
        gemm_core<128, 1>(p.ahi[z], p.alo[z], E_DIM, p.bhi[z], p.blo[z], E_DIM,
                          nullptr, p.chi[z], p.clo[z], E_DIM, p.bias[z], 1.0f, E_DIM);
}

// ===========================================================================
// FUSED ATTENTION (64-row tiles, 2 CTAs/SM): per CTA = (bh, 64 t-rows).
// s-loop in 64-chunks, 2-stage K/V pipeline.
// QK 3-term MMA -> exp -> E-hi staged+coalesced out -> P frags -> PV 3-term MMA.
// End: cross-warp O reduce, rowsum->invsum, normalize, write ao pair.
// ===========================================================================
__global__ __launch_bounds__(256, 2) void fused_attn() {
    constexpr int SKQ = 72, SKC = 72, SEW = 72;
    constexpr int QHI = 0;
    constexpr int QLO = 64 * SKQ;                  // 4608
    constexpr int STG = 2 * 64 * SKQ;              // 9216
    constexpr int SSZ = 4 * 64 * SKC;              // 18432 per stage
    constexpr int KHI = 0, KLO = 64 * SKC, VHI = 2 * 64 * SKC, VLO = 3 * 64 * SKC;
    constexpr int SE  = STG + 2 * SSZ;             // 46080
    // total = SE + 64*SEW = 50688 elems = 101376 B

    extern __shared__ __nv_bfloat16 sm[];
    const uint32_t sb = smem_u32(sm);

    const int tid = threadIdx.x;
    const int wid = tid >> 5;
    const int lane = tid & 31;
    const int wm0 = (wid >> 1) * 16;           // 4 m-groups x 16 rows
    const int wn0 = (wid & 1) * 32;
    const int z = blockIdx.z;                  // bh
    const int b = z >> 4, h = z & 15;
    const int t0 = blockIdx.x * 64;

    const __nv_bfloat16* Qh = g_qhi + (size_t)b * 1024 + h * 64 + (size_t)t0 * 2048;
    const __nv_bfloat16* Ql = g_qlo + (size_t)b * 1024 + h * 64 + (size_t)t0 * 2048;
    const __nv_bfloat16* Kh = g_khi + (size_t)b * 1024 + h * 64;
    const __nv_bfloat16* Kl = g_klo + (size_t)b * 1024 + h * 64;
    const __nv_bfloat16* Vh = g_vthi + (size_t)z * HD * S_LEN;
    const __nv_bfloat16* Vl = g_vtlo + (size_t)z * HD * S_LEN;
    __nv_bfloat16* Eh = g_phi + (size_t)z * T_LEN * S_LEN + (size_t)t0 * 2048;

    // Q tile load (64 x 64 hi/lo): 512 chunks per plane
#pragma unroll
    for (int l = 0; l < 2; l++) {
        int idx = tid + l * 256;
        int r = idx >> 3, c = idx & 7;
        cp16(sb + (uint32_t)(QHI + r * SKQ + c * 8) * 2, Qh + (size_t)r * 2048 + c * 8);
        cp16(sb + (uint32_t)(QLO + r * SKQ + c * 8) * 2, Ql + (size_t)r * 2048 + c * 8);
    }

    auto load_stage = [&](int sc, int st) {
        const uint32_t s0 = sb + (uint32_t)(STG + st * SSZ) * 2;
        const size_t srow = (size_t)sc * 64 * 2048;
#pragma unroll
        for (int l = 0; l < 2; l++) {
            int idx = tid + l * 256;
            int r = idx >> 3, c = idx & 7;
            size_t gk = srow + (size_t)r * 2048 + c * 8;
            size_t gv = (size_t)r * 2048 + sc * 64 + c * 8;
            uint32_t so = (uint32_t)(r * SKC + c * 8) * 2;
            cp16(s0 + (uint32_t)KHI * 2 + so, Kh + gk);
            cp16(s0 + (uint32_t)KLO * 2 + so, Kl + gk);
            cp16(s0 + (uint32_t)VHI * 2 + so, Vh + gv);
            cp16(s0 + (uint32_t)VLO * 2 + so, Vl + gv);
        }
    };

    load_stage(0, 0);
    CP_COMMIT();

    float acc_o[8][4];
#pragma unroll
    for (int j = 0; j < 8; j++)
#pragma unroll
        for (int q = 0; q < 4; q++) acc_o[j][q] = 0.0f;
    float rowpart[2] = {0.f, 0.f};

    const int a_row = lane & 15;
    const int a_col = (lane >> 4) << 3;
    const int b_row = (lane & 7) + ((lane >> 4) << 3);
    const int b_col = ((lane >> 3) & 1) << 3;
    const int er = lane >> 2;
    const int ec = (lane & 3) * 2;

    for (int sc = 0; sc < 32; ++sc) {
        const int st = sc & 1;
        if (sc + 1 < 32) { load_stage(sc + 1, st ^ 1); CP_COMMIT(); CP_WAIT1(); }
        else             { CP_WAIT0(); }
        __syncthreads();

        const uint32_t sK = sb + (uint32_t)(STG + st * SSZ) * 2;

        // --- QK: 64x64 scores chunk, 3-term, k over d=64 ---
        float acc_s[4][4];
#pragma unroll
        for (int j = 0; j < 4; j++)
#pragma unroll
            for (int q = 0; q < 4; q++) acc_s[j][q] = 0.0f;

#pragma unroll
        for (int kk = 0; kk < 4; kk++) {
            uint32_t ah[4], al[4];
            uint32_t ea = (uint32_t)((wm0 + a_row) * SKQ + kk * 16 + a_col) * 2;
            ldm_x4(ah, sb + (uint32_t)QHI * 2 + ea);
            ldm_x4(al, sb + (uint32_t)QLO * 2 + ea);
#pragma unroll
            for (int pi = 0; pi < 2; pi++) {
                uint32_t bh4[4], bl4[4];
                uint32_t eb = (uint32_t)((wn0 + pi * 16 + b_row) * SKC + kk * 16 + b_col) * 2;
                ldm_x4(bh4, sK + (uint32_t)KHI * 2 + eb);
                ldm_x4(bl4, sK + (uint32_t)KLO * 2 + eb);
                uint32_t bh0[2] = {bh4[0], bh4[1]}, bh1[2] = {bh4[2], bh4[3]};
                uint32_t bl0[2] = {bl4[0], bl4[1]}, bl1[2] = {bl4[2], bl4[3]};
                mma16816(acc_s[2 * pi + 0], ah, bh0);
                mma16816(acc_s[2 * pi + 1], ah, bh1);
                mma16816(acc_s[2 * pi + 0], ah, bl0);
                mma16816(acc_s[2 * pi + 1], ah, bl1);
                mma16816(acc_s[2 * pi + 0], al, bh0);
                mma16816(acc_s[2 * pi + 1], al, bh1);
            }
        }

        // --- exp, rowsum partials, stage E-hi ---
#pragma unroll
        for (int fi = 0; fi < 4; fi++) {
            float e0 = __expf(acc_s[fi][0] * 0.125f);
            float e1 = __expf(acc_s[fi][1] * 0.125f);
            float e2 = __expf(acc_s[fi][2] * 0.125f);
            float e3 = __expf(acc_s[fi][3] * 0.125f);
            acc_s[fi][0] = e0; acc_s[fi][1] = e1;
            acc_s[fi][2] = e2; acc_s[fi][3] = e3;
            rowpart[0] += e0 + e1;
            rowpart[1] += e2 + e3;
            int row = wm0 + er;
            int col = wn0 + fi * 8 + ec;
            *(unsigned*)&sm[SE + row * SEW + col] =
                pack2(__float2bfloat16(e0), __float2bfloat16(e1));
            *(unsigned*)&sm[SE + (row + 8) * SEW + col] =
                pack2(__float2bfloat16(e2), __float2bfloat16(e3));
        }

        // --- PV: P(64 x 64chunk) @ V(64chunk x 64d), k = warp's 32 s ---
#pragma unroll
        for (int kp = 0; kp < 2; kp++) {
            uint32_t ph[4], pl[4];
            {
                const float* c0 = acc_s[2 * kp];
                const float* c1 = acc_s[2 * kp + 1];
                __nv_bfloat16 ha, la, hb, lb2;
                split1(c0[0], ha, la); split1(c0[1], hb, lb2);
                ph[0] = pack2(ha, hb); pl[0] = pack2(la, lb2);
                split1(c0[2], ha, la); split1(c0[3], hb, lb2);
                ph[1] = pack2(ha, hb); pl[1] = pack2(la, lb2);
                split1(c1[0], ha, la); split1(c1[1], hb, lb2);
                ph[2] = pack2(ha, hb); pl[2] = pack2(la, lb2);
                split1(c1[2], ha, la); split1(c1[3], hb, lb2);
                ph[3] = pack2(ha, hb); pl[3] = pack2(la, lb2);
            }
#pragma unroll
            for (int nt = 0; nt < 4; nt++) {
                uint32_t vh4[4], vl4[4];
                uint32_t eb = (uint32_t)((nt * 16 + b_row) * SKC + wn0 + kp * 16 + b_col) * 2;
                ldm_x4(vh4, sK + (uint32_t)VHI * 2 + eb);
                ldm_x4(vl4, sK + (uint32_t)VLO * 2 + eb);
                uint32_t vh0[2] = {vh4[0], vh4[1]}, vh1[2] = {vh4[2], vh4[3]};
                uint32_t vl0[2] = {vl4[0], vl4[1]}, vl1[2] = {vl4[2], vl4[3]};
                mma16816(acc_o[2 * nt + 0], ph, vh0);
                mma16816(acc_o[2 * nt + 1], ph, vh1);
                mma16816(acc_o[2 * nt + 0], ph, vl0);
                mma16816(acc_o[2 * nt + 1], ph, vl1);
                mma16816(acc_o[2 * nt + 0], pl, vh0);
                mma16816(acc_o[2 * nt + 1], pl, vh1);
            }
        }

        __syncthreads();
        // --- coalesced E-hi copy-out (64 rows x 64 cols) ---
#pragma unroll
        for (int l = 0; l < 2; l++) {
            int idx = tid + l * 256;
            int r = idx >> 3, c8 = idx & 7;
            uint4 v = *(uint4*)&sm[SE + r * SEW + c8 * 8];
            *(uint4*)(Eh + (size_t)r * 2048 + sc * 64 + c8 * 8) = v;
        }
    }

    // --- row sums -> invsum ---
    __shared__ float psmem[64][2];
    __shared__ float sinv[64];
#pragma unroll
    for (int rh = 0; rh < 2; rh++) {
        float v = rowpart[rh];
        v += __shfl_xor_sync(0xffffffffu, v, 1);
        v += __shfl_xor_sync(0xffffffffu, v, 2);
        if ((lane & 3) == 0)
            psmem[wm0 + rh * 8 + er][wid & 1] = v;
    }
    __syncthreads();
    if (tid < 64) {
        float s = psmem[tid][0] + psmem[tid][1];
        float inv = 1.0f / s;
        sinv[tid] = inv;
        g_invsum[(size_t)z * T_LEN + t0 + tid] = inv;
    }

    // --- O reduce across the two n-half warps ---
    float* sO = (float*)(sm + STG);        // 64 x 68 fp32 (aliases dead stages)
    if ((wid & 1) == 0) {
#pragma unroll
        for (int nt8 = 0; nt8 < 8; nt8++) {
            int row = wm0 + er;
            int col = nt8 * 8 + ec;
            *(float2*)&sO[row * 68 + col] = make_float2(acc_o[nt8][0], acc_o[nt8][1]);
            *(float2*)&sO[(row + 8) * 68 + col] = make_float2(acc_o[nt8][2], acc_o[nt8][3]);
        }
    }
    __syncthreads();
    if ((wid & 1) == 1) {
#pragma unroll
        for (int nt8 = 0; nt8 < 8; nt8++) {
            int row = wm0 + er;
            int col = nt8 * 8 + ec;
            float2 p0 = *(float2*)&sO[row * 68 + col];
            float2 p1 = *(float2*)&sO[(row + 8) * 68 + col];
            float i0 = sinv[row], i1 = sinv[row + 8];
            float y0 = (p0.x + acc_o[nt8][0]) * i0;
            float y1 = (p0.y + acc_o[nt8][1]) * i0;
            float y2 = (p1.x + acc_o[nt8][2]) * i1;
            float y3 = (p1.y + acc_o[nt8][3]) * i1;
            __nv_bfloat16 h0, l0, h1, l1, h2, l2, h3, l3;
            split1(y0, h0, l0); split1(y1, h1, l1);
            split1(y2, h2, l2); split1(y3, h3, l3);
            size_t o0 = (size_t)(t0 + row) * 2048 + (size_t)z * 64 + col;
            size_t o1 = (size_t)(t0 + row + 8) * 2048 + (size_t)z * 64 + col;
            *(unsigned*)(g_aohi + o0) = pack2(h0, h1);
            *(unsigned*)(g_aolo + o0) = pack2(l0, l1);
            *(unsigned*)(g_aohi + o1) = pack2(h2, h3);
            *(unsigned*)(g_aolo + o1) = pack2(l2, l3);
        }
    }
}

// ---------------------------------------------------------------------------
// Merged weff: Weff = w + lb@la -> hi/lo pair
// ---------------------------------------------------------------------------
struct WeffPtrs { const float* w[4]; const float* la[4]; const float* lb[4]; };
__global__ __launch_bounds__(256) void weff_all(WeffPtrs p) {
    const int widx = blockIdx.y;
    int idx = blockIdx.x * 256 + threadIdx.x;
    int j = idx & (E_DIM - 1);
    int i = idx >> 10;
    float acc = p.w[widx][idx];
#pragma unroll
    for (int r = 0; r < R_RANK; r++)
        acc += p.lb[widx][i * R_RANK + r] * p.la[widx][r * E_DIM + j];
    __nv_bfloat16 h, l;
    split1(acc, h, l);
    g_whi[widx][idx] = h;
    g_wlo[widx][idx] = l;
}

// ---------------------------------------------------------------------------
// Merged input fp32 -> hi/lo pair
// ---------------------------------------------------------------------------
struct InPtrs { const float* in[3]; };
__global__ __launch_bounds__(256) void cvt_all(InPtrs p) {
    const int which = blockIdx.y;
    int i = blockIdx.x * 256 + threadIdx.x;
    float4 v = ((const float4*)p.in[which])[i];
    __nv_bfloat16 hx, lx, hy, ly, hz, lz, hw, lw;
    split1(v.x, hx, lx); split1(v.y, hy, ly);
    split1(v.z, hz, lz); split1(v.w, hw, lw);
    ((uint2*)g_ihi[which])[i] = make_uint2(pack2(hx, hy), pack2(hz, hw));
    ((uint2*)g_ilo[which])[i] = make_uint2(pack2(lx, ly), pack2(lz, lw));
}

// ---------------------------------------------------------------------------
// Transpose V -> per-head V^T hi/lo
// ---------------------------------------------------------------------------
__global__ void vt_kernel() {
    __shared__ float t[32][33];
    const int z = blockIdx.z;
    const int b = z >> 4, h = z & 15;
    const int s0 = blockIdx.x * 32;
    const int d0 = blockIdx.y * 32;
    const int tx = threadIdx.x, ty = threadIdx.y;
#pragma unroll
    for (int i = 0; i < 4; i++) {
        int s = s0 + ty + i * 8;
        t[ty + i * 8][tx] = g_v[((size_t)s * B_SZ + b) * E_DIM + h * HD + d0 + tx];
    }
    __syncthreads();
#pragma unroll
    for (int i = 0; i < 4; i++) {
        int d = d0 + ty + i * 8;
        float x = t[tx][ty + i * 8];
        __nv_bfloat16 hh, ll;
        split1(x, hh, ll);
        size_t o = ((size_t)z * HD + d) * S_LEN + s0 + tx;
        g_vthi[o] = hh;
        g_vtlo[o] = ll;
    }
}

// ---------------------------------------------------------------------------
// attn_w mean (E-hi, invsum): one block per (b,t)
// ---------------------------------------------------------------------------
__global__ __launch_bounds__(256) void mean_kernel(float* __restrict__ outMean) {
    const int bt = blockIdx.x;
    const int b = bt >> 11, t = bt & 2047;
    const int tid = threadIdx.x;

    __shared__ float wsc[16];
    if (tid < 16)
        wsc[tid] = g_invsum[(size_t)(b * 16 + tid) * T_LEN + t] * (1.0f / 16.0f);
    __syncthreads();

    float a0[4] = {0.f, 0.f, 0.f, 0.f};
    float a1[4] = {0.f, 0.f, 0.f, 0.f};
#pragma unroll 4
    for (int h = 0; h < 16; h++) {
        const size_t base = ((size_t)(b * 16 + h) * T_LEN + t) * S_LEN;
        const float wh = wsc[h];
        uint2 hi0 = ((const uint2*)(g_phi + base))[tid];
        uint2 hi1 = ((const uint2*)(g_phi + base))[tid + 256];
        float2 hA = unp2(hi0.x), hB = unp2(hi0.y);
        a0[0] += hA.x * wh; a0[1] += hA.y * wh;
        a0[2] += hB.x * wh; a0[3] += hB.y * wh;
        hA = unp2(hi1.x); hB = unp2(hi1.y);
        a1[0] += hA.x * wh; a1[1] += hA.y * wh;
        a1[2] += hB.x * wh; a1[3] += hB.y * wh;
    }

    float4* mrow = (float4*)(outMean + (size_t)bt * S_LEN);
    mrow[tid] = make_float4(a0[0], a0[1], a0[2], a0[3]);
    mrow[tid + 256] = make_float4(a1[0], a1[1], a1[2], a1[3]);
}

// ---------------------------------------------------------------------------
extern "C" void kernel_launch(void* const* d_in, const int* in_sizes, int n_in,
                              void* d_out, int out_size) {
    const float* query = (const float*)d_in[0];
    const float* key   = (const float*)d_in[1];
    const float* value = (const float*)d_in[2];
    const float* w[4]    = {(const float*)d_in[3],  (const float*)d_in[7],
                            (const float*)d_in[11], (const float*)d_in[15]};
    const float* bias[4] = {(const float*)d_in[4],  (const float*)d_in[8],
                            (const float*)d_in[12], (const float*)d_in[16]};
    const float* la[4]   = {(const float*)d_in[5],  (const float*)d_in[9],
                            (const float*)d_in[13], (const float*)d_in[17]};
    const float* lb[4]   = {(const float*)d_in[6],  (const float*)d_in[10],
                            (const float*)d_in[14], (const float*)d_in[18]};
    float* out = (float*)d_out;

    __nv_bfloat16 *p_whi, *p_wlo, *p_ihi, *p_ilo, *p_qhi, *p_qlo, *p_khi, *p_klo;
    __nv_bfloat16 *p_aohi, *p_aolo;
    float *p_v;
    cudaGetSymbolAddress((void**)&p_whi, g_whi);
    cudaGetSymbolAddress((void**)&p_wlo, g_wlo);
    cudaGetSymbolAddress((void**)&p_ihi, g_ihi);
    cudaGetSymbolAddress((void**)&p_ilo, g_ilo);
    cudaGetSymbolAddress((void**)&p_qhi, g_qhi);
    cudaGetSymbolAddress((void**)&p_qlo, g_qlo);
    cudaGetSymbolAddress((void**)&p_khi, g_khi);
    cudaGetSymbolAddress((void**)&p_klo, g_klo);
    cudaGetSymbolAddress((void**)&p_aohi, g_aohi);
    cudaGetSymbolAddress((void**)&p_aolo, g_aolo);
    cudaGetSymbolAddress((void**)&p_v, g_v);

    const size_t WSZ = (size_t)E_DIM * E_DIM;
    const size_t ISZ = (size_t)M_ROWS * E_DIM;

    const int SMEM128 = 2 * (2 * 128 * 40 + 2 * 128 * 40) * 2;  // 81920
    const int SMEM_F  = 101376;
    cudaFuncSetAttribute(gemm_pair<128, 0>, cudaFuncAttributeMaxDynamicSharedMemorySize, SMEM128);
    cudaFuncSetAttribute(proj_gemm, cudaFuncAttributeMaxDynamicSharedMemorySize, SMEM128);
    cudaFuncSetAttribute(fused_attn, cudaFuncAttributeMaxDynamicSharedMemorySize, SMEM_F);

    // Fold LoRA
    WeffPtrs wp;
    for (int i = 0; i < 4; i++) { wp.w[i] = w[i]; wp.la[i] = la[i]; wp.lb[i] = lb[i]; }
    weff_all<<<dim3(E_DIM * E_DIM / 256, 4), 256>>>(wp);

    // Inputs -> pair
    InPtrs ip = {{query, key, value}};
    cvt_all<<<dim3(ISZ / 4 / 256, 3), 256>>>(ip);

    // Q/K/V projections
    ProjPtrs pp;
    for (int zi = 0; zi < 3; zi++) {
        pp.ahi[zi] = p_ihi + zi * ISZ;
        pp.alo[zi] = p_ilo + zi * ISZ;
        pp.bhi[zi] = p_whi + zi * WSZ;
        pp.blo[zi] = p_wlo + zi * WSZ;
        pp.bias[zi] = bias[zi];
    }
    pp.cf[0] = nullptr; pp.chi[0] = p_qhi; pp.clo[0] = p_qlo; pp.outmode[0] = 1;
    pp.cf[1] = nullptr; pp.chi[1] = p_khi; pp.clo[1] = p_klo; pp.outmode[1] = 1;
    pp.cf[2] = p_v;     pp.chi[2] = nullptr; pp.clo[2] = nullptr; pp.outmode[2] = 0;
    proj_gemm<<<dim3(8, 32, 3), 256, SMEM128>>>(pp);

    // V^T pair
    vt_kernel<<<dim3(S_LEN / 32, HD / 32, BH), dim3(32, 8)>>>();

    // Fused attention (64-row tiles, 2 CTAs/SM): E-hi + invsum + ao pair
    fused_attn<<<dim3(32, 1, 32), 256, SMEM_F>>>();

    // attn_w mean -> out tail
    mean_kernel<<<B_SZ * T_LEN, 256>>>(out + (size_t)T_LEN * B_SZ * E_DIM);

    // Output projection -> d_out
    gemm_pair<128, 0><<<dim3(8, 32, 1), 256, SMEM128>>>(
        p_aohi, p_aolo, E_DIM,
        p_whi + 3 * WSZ, p_wlo + 3 * WSZ, E_DIM,
        out, nullptr, nullptr, E_DIM, bias[3], 1.0f, E_DIM);
}